// round 15
// baseline (speedup 1.0000x reference)
#include <cuda_runtime.h>
#include <cuda_fp16.h>
#include <mma.h>

using namespace nvcuda;

#define D      128          // feature dim (D_IN == D_OUT == 128)
#define D4     32           // D / 4
#define MAXN   10000
#define MAXE   640000
#define CAP    256          // bucket capacity per row (Poisson(64); 24-sigma margin)
#define WST    136          // padded smem stride in halves (136*2=272B, 16B-aligned)

// ---------------- device scratch (no allocations allowed) ----------------
__device__ __align__(16) uint2 g_h2[MAXN * 32];      // h = x @ W, fp16 packed
__device__ int   g_cur[MAXN];                        // per-row fill cursor
__device__ __align__(16) uint2 g_bucket[MAXN * CAP]; // (col, val-bits) per row

// ---------------- GEMM: h = x @ W via HMMA (fp16 in, fp32 acc) ------------
// gemm blocks: 256 threads (8 warps), tile = 128 rows x 128 cols.
// Extra blocks past gemm_blocks zero g_cur.
extern __shared__ __half s_half[];

__global__ void gemm_zero_kernel(const float* __restrict__ x,
                                 const float* __restrict__ w,
                                 int n, int gemm_blocks) {
    if (blockIdx.x >= gemm_blocks) {
        int i = (blockIdx.x - gemm_blocks) * blockDim.x + threadIdx.x;
        if (i < n) g_cur[i] = 0;
        return;
    }

    __half* wS = s_half;              // [128][WST]
    __half* xS = s_half + D * WST;    // [128][WST]

    const int t       = threadIdx.x;
    const int rowbase = blockIdx.x * 128;

    // convert W (128x128 fp32) -> fp16 smem
    const float4* w4 = (const float4*)w;
    for (int i = t; i < D * D4; i += 256) {
        int r = i >> 5, c4 = i & 31;
        float4 v = w4[i];
        __half2 lo = __float22half2_rn(make_float2(v.x, v.y));
        __half2 hi = __float22half2_rn(make_float2(v.z, v.w));
        __half2* dst = (__half2*)(wS + r * WST + c4 * 4);
        dst[0] = lo;
        dst[1] = hi;
    }

    // convert x tile (128x128 fp32) -> fp16 smem, zero-pad rows >= n
    const float4* x4 = (const float4*)x;
    for (int i = t; i < 128 * D4; i += 256) {
        int r = i >> 5, c4 = i & 31;
        int gr = rowbase + r;
        float4 v = (gr < n) ? x4[gr * D4 + c4] : make_float4(0.f, 0.f, 0.f, 0.f);
        __half2 lo = __float22half2_rn(make_float2(v.x, v.y));
        __half2 hi = __float22half2_rn(make_float2(v.z, v.w));
        __half2* dst = (__half2*)(xS + r * WST + c4 * 4);
        dst[0] = lo;
        dst[1] = hi;
    }
    __syncthreads();

    const int warp    = t >> 5;
    const int row0    = rowbase + warp * 16;   // this warp's 16-row stripe
    if (row0 >= n) return;                      // n % 16 == 0 -> full tiles only

    wmma::fragment<wmma::accumulator, 16, 16, 16, float> acc[8];
#pragma unroll
    for (int c = 0; c < 8; c++) wmma::fill_fragment(acc[c], 0.0f);

    wmma::fragment<wmma::matrix_a, 16, 16, 16, __half, wmma::row_major> afrag;
    wmma::fragment<wmma::matrix_b, 16, 16, 16, __half, wmma::row_major> bfrag;

#pragma unroll
    for (int k = 0; k < 8; k++) {
        wmma::load_matrix_sync(afrag, xS + (warp * 16) * WST + k * 16, WST);
#pragma unroll
        for (int c = 0; c < 8; c++) {
            wmma::load_matrix_sync(bfrag, wS + (k * 16) * WST + c * 16, WST);
            wmma::mma_sync(acc[c], afrag, bfrag, acc[c]);
        }
    }

    // convert fp32 acc -> fp16, store straight to global g_h2 (stride 128)
    __half* hout = (__half*)g_h2 + row0 * D;
    wmma::fragment<wmma::accumulator, 16, 16, 16, __half> hacc;
#pragma unroll
    for (int c = 0; c < 8; c++) {
#pragma unroll
        for (int i = 0; i < hacc.num_elements; i++)
            hacc.x[i] = __float2half(acc[c].x[i]);
        wmma::store_matrix_sync(hout + c * 16, hacc, D, wmma::mem_row_major);
    }
}

// ---------------- direct bucket scatter: 4 edges per thread ---------------
__global__ void scatter_kernel(const int* __restrict__ row,
                               const int* __restrict__ col,
                               const float* __restrict__ val, int E) {
    const int base = (blockIdx.x * blockDim.x + threadIdx.x) * 4;
    if (base >= E) return;

    if (base + 4 <= E) {
        int4   r4 = *(const int4*)(row + base);
        int4   c4 = *(const int4*)(col + base);
        float4 v4 = *(const float4*)(val + base);

        int p0 = atomicAdd(&g_cur[r4.x], 1);
        int p1 = atomicAdd(&g_cur[r4.y], 1);
        int p2 = atomicAdd(&g_cur[r4.z], 1);
        int p3 = atomicAdd(&g_cur[r4.w], 1);

        if (p0 < CAP) g_bucket[r4.x * CAP + p0] = make_uint2((unsigned)c4.x, __float_as_uint(v4.x));
        if (p1 < CAP) g_bucket[r4.y * CAP + p1] = make_uint2((unsigned)c4.y, __float_as_uint(v4.y));
        if (p2 < CAP) g_bucket[r4.z * CAP + p2] = make_uint2((unsigned)c4.z, __float_as_uint(v4.z));
        if (p3 < CAP) g_bucket[r4.w * CAP + p3] = make_uint2((unsigned)c4.w, __float_as_uint(v4.w));
    } else {
        for (int i = base; i < E; i++) {
            int r = row[i];
            int p = atomicAdd(&g_cur[r], 1);
            if (p < CAP) g_bucket[r * CAP + p] = make_uint2((unsigned)col[i], __float_as_uint(val[i]));
        }
    }
}

// ---------------- SpMM: pull-based, one warp per output row ---------------
__global__ void spmm_kernel(const float* __restrict__ bias,
                            float* __restrict__ out, int n) {
    const int warp = (blockIdx.x * blockDim.x + threadIdx.x) >> 5;
    const int lane = threadIdx.x & 31;
    if (warp >= n) return;

    int cnt = g_cur[warp];
    if (cnt > CAP) cnt = CAP;
    const uint2* __restrict__ edges = g_bucket + warp * CAP;

    float4 acc = make_float4(0.f, 0.f, 0.f, 0.f);

    int e = 0;
    for (; e + 32 <= cnt; e += 32) {
        uint2 ed = edges[e + lane];
        int   c  = (int)ed.x;
        float v  = __uint_as_float(ed.y);
#pragma unroll 8
        for (int j = 0; j < 32; j++) {
            int   cj = __shfl_sync(0xffffffffu, c, j);
            float vj = __shfl_sync(0xffffffffu, v, j);
            uint2 hv = g_h2[cj * 32 + lane];
            __half2 hl = *(__half2*)&hv.x;
            __half2 hh = *(__half2*)&hv.y;
            float2 f0 = __half22float2(hl);
            float2 f1 = __half22float2(hh);
            acc.x += vj * f0.x;
            acc.y += vj * f0.y;
            acc.z += vj * f1.x;
            acc.w += vj * f1.y;
        }
    }
    int rem = cnt - e;
    if (rem > 0) {
        int   c = 0;
        float v = 0.f;
        if (lane < rem) {
            uint2 ed = edges[e + lane];
            c = (int)ed.x;
            v = __uint_as_float(ed.y);
        }
        for (int j = 0; j < rem; j++) {
            int   cj = __shfl_sync(0xffffffffu, c, j);
            float vj = __shfl_sync(0xffffffffu, v, j);
            uint2 hv = g_h2[cj * 32 + lane];
            __half2 hl = *(__half2*)&hv.x;
            __half2 hh = *(__half2*)&hv.y;
            float2 f0 = __half22float2(hl);
            float2 f1 = __half22float2(hh);
            acc.x += vj * f0.x;
            acc.y += vj * f0.y;
            acc.z += vj * f1.x;
            acc.w += vj * f1.y;
        }
    }

    float4 b = ((const float4*)bias)[lane];
    acc.x += b.x; acc.y += b.y; acc.z += b.z; acc.w += b.w;
    ((float4*)out)[warp * D4 + lane] = acc;
}

// ---------------- launch --------------------------------------------------
extern "C" void kernel_launch(void* const* d_in, const int* in_sizes, int n_in,
                              void* d_out, int out_size) {
    const float* x    = (const float*)d_in[0];
    const float* val  = (const float*)d_in[1];
    const float* w    = (const float*)d_in[2];
    const float* bias = (const float*)d_in[3];
    const int*   row  = (const int*)d_in[4];
    const int*   col  = (const int*)d_in[5];

    const int N = in_sizes[0] / D;   // 10000
    const int E = in_sizes[1];       // 640000

    const int GEMM_SMEM = 2 * D * WST * (int)sizeof(__half);  // ~68 KB
    cudaFuncSetAttribute(gemm_zero_kernel,
                         cudaFuncAttributeMaxDynamicSharedMemorySize, GEMM_SMEM);

    const int gemm_blocks = (N + 127) / 128;     // 79
    const int zero_blocks = (N + 255) / 256;     // 40

    gemm_zero_kernel<<<gemm_blocks + zero_blocks, 256, GEMM_SMEM>>>(x, w, N, gemm_blocks);

    const int sc_threads = (E + 3) / 4;
    scatter_kernel<<<(sc_threads + 255) / 256, 256>>>(row, col, val, E);

    spmm_kernel<<<(N + 7) / 8, 256>>>(bias, (float*)d_out, N);
}

// round 16
// speedup vs baseline: 1.0078x; 1.0078x over previous
#include <cuda_runtime.h>
#include <cuda_fp16.h>
#include <mma.h>

using namespace nvcuda;

#define D      128          // feature dim (D_IN == D_OUT == 128)
#define D4     32           // D / 4
#define MAXN   10000
#define MAXE   640000
#define CAP    256          // bucket capacity per row (Poisson(64); 24-sigma margin)
#define WST    136          // padded smem stride in halves (136*2=272B, 16B-aligned)

// ---------------- device scratch (no allocations allowed) ----------------
__device__ __align__(16) uint2 g_h2[MAXN * 32];      // h = x @ W, fp16 packed
__device__ int   g_cur[MAXN];                        // per-row fill cursor
__device__ __align__(16) uint2 g_bucket[MAXN * CAP]; // (col, val-bits) per row

// ---------------- GEMM: h = x @ W via HMMA (fp16 in, fp32 acc) ------------
// gemm blocks: 256 threads (8 warps), tile = 128 rows x 128 cols.
// Extra blocks past gemm_blocks zero g_cur.
extern __shared__ __half s_half[];

__global__ void gemm_zero_kernel(const float* __restrict__ x,
                                 const float* __restrict__ w,
                                 int n, int gemm_blocks) {
    if (blockIdx.x >= gemm_blocks) {
        int i = (blockIdx.x - gemm_blocks) * blockDim.x + threadIdx.x;
        if (i < n) g_cur[i] = 0;
        return;
    }

    __half* wS = s_half;              // [128][WST]
    __half* xS = s_half + D * WST;    // [128][WST]

    const int t       = threadIdx.x;
    const int rowbase = blockIdx.x * 128;

    // convert W (128x128 fp32) -> fp16 smem
    const float4* w4 = (const float4*)w;
    for (int i = t; i < D * D4; i += 256) {
        int r = i >> 5, c4 = i & 31;
        float4 v = w4[i];
        __half2 lo = __float22half2_rn(make_float2(v.x, v.y));
        __half2 hi = __float22half2_rn(make_float2(v.z, v.w));
        __half2* dst = (__half2*)(wS + r * WST + c4 * 4);
        dst[0] = lo;
        dst[1] = hi;
    }

    // convert x tile (128x128 fp32) -> fp16 smem, zero-pad rows >= n
    const float4* x4 = (const float4*)x;
    for (int i = t; i < 128 * D4; i += 256) {
        int r = i >> 5, c4 = i & 31;
        int gr = rowbase + r;
        float4 v = (gr < n) ? x4[gr * D4 + c4] : make_float4(0.f, 0.f, 0.f, 0.f);
        __half2 lo = __float22half2_rn(make_float2(v.x, v.y));
        __half2 hi = __float22half2_rn(make_float2(v.z, v.w));
        __half2* dst = (__half2*)(xS + r * WST + c4 * 4);
        dst[0] = lo;
        dst[1] = hi;
    }
    __syncthreads();

    const int warp    = t >> 5;
    const int row0    = rowbase + warp * 16;   // this warp's 16-row stripe
    if (row0 >= n) return;                      // n % 16 == 0 -> full tiles only

    wmma::fragment<wmma::accumulator, 16, 16, 16, float> acc[8];
#pragma unroll
    for (int c = 0; c < 8; c++) wmma::fill_fragment(acc[c], 0.0f);

    wmma::fragment<wmma::matrix_a, 16, 16, 16, __half, wmma::row_major> afrag;
    wmma::fragment<wmma::matrix_b, 16, 16, 16, __half, wmma::row_major> bfrag;

#pragma unroll
    for (int k = 0; k < 8; k++) {
        wmma::load_matrix_sync(afrag, xS + (warp * 16) * WST + k * 16, WST);
#pragma unroll
        for (int c = 0; c < 8; c++) {
            wmma::load_matrix_sync(bfrag, wS + (k * 16) * WST + c * 16, WST);
            wmma::mma_sync(acc[c], afrag, bfrag, acc[c]);
        }
    }

    // convert fp32 acc -> fp16, store straight to global g_h2 (stride 128)
    __half* hout = (__half*)g_h2 + row0 * D;
    wmma::fragment<wmma::accumulator, 16, 16, 16, __half> hacc;
#pragma unroll
    for (int c = 0; c < 8; c++) {
#pragma unroll
        for (int i = 0; i < hacc.num_elements; i++)
            hacc.x[i] = __float2half(acc[c].x[i]);
        wmma::store_matrix_sync(hout + c * 16, hacc, D, wmma::mem_row_major);
    }
}

// ---------------- direct bucket scatter: 4 edges per thread ---------------
__global__ void scatter_kernel(const int* __restrict__ row,
                               const int* __restrict__ col,
                               const float* __restrict__ val, int E) {
    const int base = (blockIdx.x * blockDim.x + threadIdx.x) * 4;
    if (base >= E) return;

    if (base + 4 <= E) {
        int4   r4 = *(const int4*)(row + base);
        int4   c4 = *(const int4*)(col + base);
        float4 v4 = *(const float4*)(val + base);

        int p0 = atomicAdd(&g_cur[r4.x], 1);
        int p1 = atomicAdd(&g_cur[r4.y], 1);
        int p2 = atomicAdd(&g_cur[r4.z], 1);
        int p3 = atomicAdd(&g_cur[r4.w], 1);

        if (p0 < CAP) g_bucket[r4.x * CAP + p0] = make_uint2((unsigned)c4.x, __float_as_uint(v4.x));
        if (p1 < CAP) g_bucket[r4.y * CAP + p1] = make_uint2((unsigned)c4.y, __float_as_uint(v4.y));
        if (p2 < CAP) g_bucket[r4.z * CAP + p2] = make_uint2((unsigned)c4.z, __float_as_uint(v4.z));
        if (p3 < CAP) g_bucket[r4.w * CAP + p3] = make_uint2((unsigned)c4.w, __float_as_uint(v4.w));
    } else {
        for (int i = base; i < E; i++) {
            int r = row[i];
            int p = atomicAdd(&g_cur[r], 1);
            if (p < CAP) g_bucket[r * CAP + p] = make_uint2((unsigned)col[i], __float_as_uint(val[i]));
        }
    }
}

// ---------------- SpMM: pull-based, one warp per output row ---------------
__global__ void spmm_kernel(const float* __restrict__ bias,
                            float* __restrict__ out, int n) {
    const int warp = (blockIdx.x * blockDim.x + threadIdx.x) >> 5;
    const int lane = threadIdx.x & 31;
    if (warp >= n) return;

    int cnt = g_cur[warp];
    if (cnt > CAP) cnt = CAP;
    const uint2* __restrict__ edges = g_bucket + warp * CAP;

    float4 acc = make_float4(0.f, 0.f, 0.f, 0.f);

    int e = 0;
    for (; e + 32 <= cnt; e += 32) {
        uint2 ed = edges[e + lane];
        int   c  = (int)ed.x;
        float v  = __uint_as_float(ed.y);
#pragma unroll 8
        for (int j = 0; j < 32; j++) {
            int   cj = __shfl_sync(0xffffffffu, c, j);
            float vj = __shfl_sync(0xffffffffu, v, j);
            uint2 hv = g_h2[cj * 32 + lane];
            __half2 hl = *(__half2*)&hv.x;
            __half2 hh = *(__half2*)&hv.y;
            float2 f0 = __half22float2(hl);
            float2 f1 = __half22float2(hh);
            acc.x += vj * f0.x;
            acc.y += vj * f0.y;
            acc.z += vj * f1.x;
            acc.w += vj * f1.y;
        }
    }
    int rem = cnt - e;
    if (rem > 0) {
        int   c = 0;
        float v = 0.f;
        if (lane < rem) {
            uint2 ed = edges[e + lane];
            c = (int)ed.x;
            v = __uint_as_float(ed.y);
        }
        for (int j = 0; j < rem; j++) {
            int   cj = __shfl_sync(0xffffffffu, c, j);
            float vj = __shfl_sync(0xffffffffu, v, j);
            uint2 hv = g_h2[cj * 32 + lane];
            __half2 hl = *(__half2*)&hv.x;
            __half2 hh = *(__half2*)&hv.y;
            float2 f0 = __half22float2(hl);
            float2 f1 = __half22float2(hh);
            acc.x += vj * f0.x;
            acc.y += vj * f0.y;
            acc.z += vj * f1.x;
            acc.w += vj * f1.y;
        }
    }

    float4 b = ((const float4*)bias)[lane];
    acc.x += b.x; acc.y += b.y; acc.z += b.z; acc.w += b.w;
    ((float4*)out)[warp * D4 + lane] = acc;
}

// ---------------- launch --------------------------------------------------
extern "C" void kernel_launch(void* const* d_in, const int* in_sizes, int n_in,
                              void* d_out, int out_size) {
    const float* x    = (const float*)d_in[0];
    const float* val  = (const float*)d_in[1];
    const float* w    = (const float*)d_in[2];
    const float* bias = (const float*)d_in[3];
    const int*   row  = (const int*)d_in[4];
    const int*   col  = (const int*)d_in[5];

    const int N = in_sizes[0] / D;   // 10000
    const int E = in_sizes[1];       // 640000

    const int GEMM_SMEM = 2 * D * WST * (int)sizeof(__half);  // ~68 KB
    cudaFuncSetAttribute(gemm_zero_kernel,
                         cudaFuncAttributeMaxDynamicSharedMemorySize, GEMM_SMEM);

    const int gemm_blocks = (N + 127) / 128;     // 79
    const int zero_blocks = (N + 255) / 256;     // 40

    gemm_zero_kernel<<<gemm_blocks + zero_blocks, 256, GEMM_SMEM>>>(x, w, N, gemm_blocks);

    const int sc_threads = (E + 3) / 4;
    scatter_kernel<<<(sc_threads + 255) / 256, 256>>>(row, col, val, E);

    spmm_kernel<<<(N + 7) / 8, 256>>>(bias, (float*)d_out, N);
}